// round 1
// baseline (speedup 1.0000x reference)
#include <cuda_runtime.h>
#include <cuda_bf16.h>

// Problem shapes
#define N_Q   65536      // B*H*W = 64*32*32
#define DIM   64
#define K_EMB 1024
#define CHUNK 128        // embeddings staged per smem chunk
#define THREADS 256

#define OUT_QV_ELEMS  (64ULL * 64ULL * 32ULL * 32ULL)   // 4194304
#define OUT_IDX_OFF   4194304ULL
#define OUT_LOSS_OFF  4259840ULL                        // 4194304 + 65536

// scratch (no cudaMalloc allowed)
__device__ double g_loss;
__device__ float  g_se2[K_EMB];

// ---------------------------------------------------------------------------
// Prep: zero loss accumulator, precompute ||e_k||^2 (square-then-add, no fma
// contraction, sequential order to approximate reference reduction)
// ---------------------------------------------------------------------------
__global__ void vq_prep(const float* __restrict__ emb) {
    int k = blockIdx.x * blockDim.x + threadIdx.x;
    if (k == 0) g_loss = 0.0;
    if (k < K_EMB) {
        const float* e = emb + k * DIM;
        float s = 0.0f;
        #pragma unroll
        for (int j = 0; j < DIM; ++j) {
            s = __fadd_rn(s, __fmul_rn(e[j], e[j]));
        }
        g_se2[k] = s;
    }
}

// ---------------------------------------------------------------------------
// Main: one thread per query. z row in registers; codebook chunks in smem
// (broadcast reads, conflict-free). d2 = (s_z - 2*dot) + s_e, same final
// rounding order as the reference; strict < keeps first-index on ties.
// ---------------------------------------------------------------------------
__global__ void __launch_bounds__(THREADS, 2)
vq_main(const float* __restrict__ z,
        const float* __restrict__ emb,
        float* __restrict__ out) {
    __shared__ float4 sE[CHUNK * (DIM / 4)];   // 128*16 float4 = 32 KB
    __shared__ double sRed[THREADS / 32];

    const int n = blockIdx.x * THREADS + threadIdx.x;   // query id

    // Load this thread's z row (16 x float4) into registers
    float zr[DIM];
    {
        const float4* zrow = reinterpret_cast<const float4*>(z + (size_t)n * DIM);
        #pragma unroll
        for (int i = 0; i < DIM / 4; ++i) {
            float4 v = __ldg(zrow + i);
            zr[4 * i + 0] = v.x;
            zr[4 * i + 1] = v.y;
            zr[4 * i + 2] = v.z;
            zr[4 * i + 3] = v.w;
        }
    }

    // s_z = sum(z*z), square-then-add, sequential
    float sz = 0.0f;
    #pragma unroll
    for (int j = 0; j < DIM; ++j) {
        sz = __fadd_rn(sz, __fmul_rn(zr[j], zr[j]));
    }

    float best = 3.4e38f;
    int   bidx = 0;

    for (int kc = 0; kc < K_EMB; kc += CHUNK) {
        __syncthreads();
        // cooperative coalesced chunk load: CHUNK*16 float4 over 256 threads
        {
            const float4* src = reinterpret_cast<const float4*>(emb + (size_t)kc * DIM);
            #pragma unroll
            for (int i = threadIdx.x; i < CHUNK * (DIM / 4); i += THREADS) {
                sE[i] = src[i];
            }
        }
        __syncthreads();

        #pragma unroll 2
        for (int k = 0; k < CHUNK; ++k) {
            const float4* e4 = sE + k * (DIM / 4);
            float a0 = 0.0f, a1 = 0.0f, a2 = 0.0f, a3 = 0.0f;
            #pragma unroll
            for (int j = 0; j < DIM / 4; ++j) {
                float4 e = e4[j];            // broadcast LDS (all lanes same addr)
                a0 = fmaf(zr[4 * j + 0], e.x, a0);
                a1 = fmaf(zr[4 * j + 1], e.y, a1);
                a2 = fmaf(zr[4 * j + 2], e.z, a2);
                a3 = fmaf(zr[4 * j + 3], e.w, a3);
            }
            float dot = __fadd_rn(__fadd_rn(a0, a1), __fadd_rn(a2, a3));
            float d2  = __fadd_rn(__fsub_rn(sz, __fmul_rn(2.0f, dot)), g_se2[kc + k]);
            if (d2 < best) { best = d2; bidx = kc + k; }
        }
    }

    // ---- outputs ----
    // n = (b*32 + h)*32 + w  ;  quantized_vector out[((b*64+d)*32+h)*32+w]
    const int w = n & 31;
    const int h = (n >> 5) & 31;
    const int b = n >> 10;
    const size_t obase = (size_t)b * 65536 + (size_t)h * 32 + w;

    const float* eb = emb + (size_t)bidx * DIM;
    double lsum = 0.0;
    #pragma unroll
    for (int d = 0; d < DIM; ++d) {
        float q = __ldg(eb + d);
        out[obase + (size_t)d * 1024] = q;      // warp-coalesced (w contiguous)
        float diff = __fsub_rn(q, zr[d]);
        lsum += (double)diff * (double)diff;
    }

    out[OUT_IDX_OFF + (size_t)n] = (float)bidx;

    // ---- loss reduction: warp shuffle -> smem -> block -> atomicAdd ----
    #pragma unroll
    for (int off = 16; off > 0; off >>= 1)
        lsum += __shfl_down_sync(0xFFFFFFFFu, lsum, off);
    const int lane = threadIdx.x & 31;
    const int wid  = threadIdx.x >> 5;
    if (lane == 0) sRed[wid] = lsum;
    __syncthreads();
    if (wid == 0) {
        double v = (lane < THREADS / 32) ? sRed[lane] : 0.0;
        #pragma unroll
        for (int off = 4; off > 0; off >>= 1)
            v += __shfl_down_sync(0xFFFFFFFFu, v, off);
        if (lane == 0) atomicAdd(&g_loss, v);
    }
}

// ---------------------------------------------------------------------------
// Finalize: loss = 1.25 * mean((q - z)^2) over B*H*W*D elements
// ---------------------------------------------------------------------------
__global__ void vq_fin(float* __restrict__ out) {
    if (threadIdx.x == 0 && blockIdx.x == 0) {
        double mean = g_loss / (double)OUT_QV_ELEMS;
        out[OUT_LOSS_OFF] = (float)(mean * 0.25 + mean * 1.0);
    }
}

extern "C" void kernel_launch(void* const* d_in, const int* in_sizes, int n_in,
                              void* d_out, int out_size) {
    const float* z   = (const float*)d_in[0];
    const float* emb = (const float*)d_in[1];
    float* out = (float*)d_out;

    vq_prep<<<(K_EMB + 255) / 256, 256>>>(emb);
    vq_main<<<N_Q / THREADS, THREADS>>>(z, emb, out);
    vq_fin<<<1, 32>>>(out);
}

// round 2
// speedup vs baseline: 1.9446x; 1.9446x over previous
#include <cuda_runtime.h>
#include <cuda_bf16.h>

// Shapes
#define N_Q    65536
#define DIM    64
#define K_EMB  1024
#define QB     128        // queries per block
#define NWARP  8
#define THREADS 256
#define CHUNK  64         // codes per smem stage
#define PAD    68         // smem row stride (floats) -> conflict-free frags

#define OUT_QV_ELEMS  (64ULL * 64ULL * 32ULL * 32ULL)   // 4194304
#define OUT_IDX_OFF   4194304ULL
#define OUT_LOSS_OFF  4259840ULL

// device scratch (no cudaMalloc allowed)
__device__ double   g_loss;
__device__ float    g_se2[K_EMB];
__device__ unsigned g_eHi[K_EMB * DIM];   // tf32 hi part of codebook
__device__ unsigned g_eLo[K_EMB * DIM];   // tf32 lo part

__device__ __forceinline__ unsigned f2tf32(float x) {
    unsigned r;
    asm("cvt.rna.tf32.f32 %0, %1;" : "=r"(r) : "f"(x));
    return r;
}

__device__ __forceinline__ void mma_tf32(float& d0, float& d1, float& d2, float& d3,
                                         unsigned a0, unsigned a1, unsigned a2, unsigned a3,
                                         unsigned b0, unsigned b1) {
    asm volatile(
        "mma.sync.aligned.m16n8k8.row.col.f32.tf32.tf32.f32 "
        "{%0,%1,%2,%3}, {%4,%5,%6,%7}, {%8,%9}, {%0,%1,%2,%3};\n"
        : "+f"(d0), "+f"(d1), "+f"(d2), "+f"(d3)
        : "r"(a0), "r"(a1), "r"(a2), "r"(a3), "r"(b0), "r"(b1));
}

// ---------------------------------------------------------------------------
// Prep: zero loss, ||e||^2 (square-then-add sequential, same as passing R1),
// and tf32 hi/lo decomposition of the codebook.
// ---------------------------------------------------------------------------
__global__ void vq_prep(const float* __restrict__ emb) {
    int t = blockIdx.x * blockDim.x + threadIdx.x;
    if (t == 0) g_loss = 0.0;
    if (t < K_EMB * DIM) {
        float v = emb[t];
        unsigned h = f2tf32(v);
        float lo = __fsub_rn(v, __uint_as_float(h));
        g_eHi[t] = h;
        g_eLo[t] = f2tf32(lo);
    }
    if (t < K_EMB) {
        const float* e = emb + t * DIM;
        float s = 0.0f;
        #pragma unroll
        for (int j = 0; j < DIM; ++j)
            s = __fadd_rn(s, __fmul_rn(e[j], e[j]));
        g_se2[t] = s;
    }
}

// ---------------------------------------------------------------------------
// Main: 128 queries/block, argmin over all 1024 codes via 3xTF32 mma.sync.
// ---------------------------------------------------------------------------
__global__ void __launch_bounds__(THREADS, 2)
vq_main(const float* __restrict__ z,
        const float* __restrict__ emb,
        float* __restrict__ out) {
    // sBuf: phase0 holds z-tile [128][PAD]; then reused as codebook stage
    // (hi[CHUNK][PAD] ++ lo[CHUNK][PAD], exactly the same 34816 bytes).
    __shared__ float  sBuf[QB * PAD];
    __shared__ float  sSz[QB];
    __shared__ float  sSe[CHUNK];
    __shared__ int    sIdx[QB];
    __shared__ double sRed[4];

    unsigned* sHi = reinterpret_cast<unsigned*>(sBuf);
    unsigned* sLo = sHi + CHUNK * PAD;

    const int tid  = threadIdx.x;
    const int wid  = tid >> 5;
    const int lane = tid & 31;
    const int gid  = lane >> 2;   // 0..7
    const int tig  = lane & 3;    // 0..3
    const int qb   = blockIdx.x * QB;

    // ---- phase 0: stage z tile, row norms, A fragments ----
    {
        const float4* src = reinterpret_cast<const float4*>(z + (size_t)qb * DIM);
        #pragma unroll
        for (int i = tid; i < QB * (DIM / 4); i += THREADS) {
            int row = i >> 4, c4 = i & 15;
            float4 v = __ldg(src + row * (DIM / 4) + c4);
            *reinterpret_cast<float4*>(&sBuf[row * PAD + 4 * c4]) = v;
        }
    }
    __syncthreads();

    if (tid < QB) {
        float s = 0.0f;
        const float* r = &sBuf[tid * PAD];
        #pragma unroll
        for (int j = 0; j < DIM; ++j)
            s = __fadd_rn(s, __fmul_rn(r[j], r[j]));
        sSz[tid] = s;
    }
    __syncthreads();

    // A fragments: rows r0 = wid*16+gid, r1 = r0+8; 8 k-steps, hi/lo
    unsigned aHi[8][4], aLo[8][4];
    const int r0 = wid * 16 + gid;
    const int r1 = r0 + 8;
    #pragma unroll
    for (int ks = 0; ks < 8; ++ks) {
        const int c = ks * 8 + tig;
        float v0 = sBuf[r0 * PAD + c];
        float v1 = sBuf[r1 * PAD + c];
        float v2 = sBuf[r0 * PAD + c + 4];
        float v3 = sBuf[r1 * PAD + c + 4];
        aHi[ks][0] = f2tf32(v0); aLo[ks][0] = f2tf32(__fsub_rn(v0, __uint_as_float(aHi[ks][0])));
        aHi[ks][1] = f2tf32(v1); aLo[ks][1] = f2tf32(__fsub_rn(v1, __uint_as_float(aHi[ks][1])));
        aHi[ks][2] = f2tf32(v2); aLo[ks][2] = f2tf32(__fsub_rn(v2, __uint_as_float(aHi[ks][2])));
        aHi[ks][3] = f2tf32(v3); aLo[ks][3] = f2tf32(__fsub_rn(v3, __uint_as_float(aHi[ks][3])));
    }
    const float sz0 = sSz[r0];
    const float sz1 = sSz[r1];
    __syncthreads();   // before overwriting sBuf with codebook stage

    float best0 = 3.4e38f, best1 = 3.4e38f;
    int   idx0  = 0,       idx1  = 0;

    for (int kb = 0; kb < K_EMB; kb += CHUNK) {
        // ---- stage codebook chunk (hi+lo) + se ----
        {
            const uint4* srcH = reinterpret_cast<const uint4*>(g_eHi + kb * DIM);
            const uint4* srcL = reinterpret_cast<const uint4*>(g_eLo + kb * DIM);
            #pragma unroll
            for (int i = tid; i < CHUNK * (DIM / 4); i += THREADS) {
                int row = i >> 4, c4 = i & 15;
                uint4 vh = srcH[i];
                uint4 vl = srcL[i];
                *reinterpret_cast<uint4*>(&sHi[row * PAD + 4 * c4]) = vh;
                *reinterpret_cast<uint4*>(&sLo[row * PAD + 4 * c4]) = vl;
            }
            if (tid < CHUNK) sSe[tid] = g_se2[kb + tid];
        }
        __syncthreads();

        #pragma unroll
        for (int nc = 0; nc < CHUNK / 8; ++nc) {
            float d0 = 0.f, d1 = 0.f, d2 = 0.f, d3 = 0.f;
            const int bbase = (nc * 8 + gid) * PAD;
            #pragma unroll
            for (int ks = 0; ks < 8; ++ks) {
                const int k0 = ks * 8 + tig;
                unsigned bh0 = sHi[bbase + k0];
                unsigned bh1 = sHi[bbase + k0 + 4];
                unsigned bl0 = sLo[bbase + k0];
                unsigned bl1 = sLo[bbase + k0 + 4];
                mma_tf32(d0, d1, d2, d3, aHi[ks][0], aHi[ks][1], aHi[ks][2], aHi[ks][3], bh0, bh1);
                mma_tf32(d0, d1, d2, d3, aHi[ks][0], aHi[ks][1], aHi[ks][2], aHi[ks][3], bl0, bl1);
                mma_tf32(d0, d1, d2, d3, aLo[ks][0], aLo[ks][1], aLo[ks][2], aLo[ks][3], bh0, bh1);
            }
            // epilogue: reference rounding fl(fl(sz - fl(2*dot)) + se)
            const int cl0 = nc * 8 + 2 * tig;
            const float se0 = sSe[cl0], se1 = sSe[cl0 + 1];
            const int code0 = kb + cl0, code1 = code0 + 1;

            float q00 = __fadd_rn(__fsub_rn(sz0, __fmul_rn(2.0f, d0)), se0);
            float q01 = __fadd_rn(__fsub_rn(sz0, __fmul_rn(2.0f, d1)), se1);
            float q10 = __fadd_rn(__fsub_rn(sz1, __fmul_rn(2.0f, d2)), se0);
            float q11 = __fadd_rn(__fsub_rn(sz1, __fmul_rn(2.0f, d3)), se1);

            if (q00 < best0) { best0 = q00; idx0 = code0; }
            if (q01 < best0) { best0 = q01; idx0 = code1; }
            if (q10 < best1) { best1 = q10; idx1 = code0; }
            if (q11 < best1) { best1 = q11; idx1 = code1; }
        }
        __syncthreads();
    }

    // ---- cross-lane argmin over the quad (cols), first-index tie-break ----
    #pragma unroll
    for (int off = 1; off <= 2; off <<= 1) {
        float ov0 = __shfl_xor_sync(0xFFFFFFFFu, best0, off);
        int   oi0 = __shfl_xor_sync(0xFFFFFFFFu, idx0, off);
        float ov1 = __shfl_xor_sync(0xFFFFFFFFu, best1, off);
        int   oi1 = __shfl_xor_sync(0xFFFFFFFFu, idx1, off);
        if (ov0 < best0 || (ov0 == best0 && oi0 < idx0)) { best0 = ov0; idx0 = oi0; }
        if (ov1 < best1 || (ov1 == best1 && oi1 < idx1)) { best1 = ov1; idx1 = oi1; }
    }
    if (tig == 0) {
        sIdx[wid * 16 + gid]     = idx0;
        sIdx[wid * 16 + gid + 8] = idx1;
    }
    __syncthreads();

    // ---- outputs: gather, STE (exact reference rounding), idx, loss ----
    double lsum = 0.0;
    if (tid < QB) {
        const int n = qb + tid;
        const int bidx = sIdx[tid];
        const int w = n & 31;
        const int h = (n >> 5) & 31;
        const int b = n >> 10;
        const size_t obase = (size_t)b * 65536 + (size_t)h * 32 + w;

        const float4* zrow = reinterpret_cast<const float4*>(z + (size_t)n * DIM);
        const float*  eb   = emb + (size_t)bidx * DIM;
        #pragma unroll
        for (int i4 = 0; i4 < DIM / 4; ++i4) {
            float4 zv = __ldg(zrow + i4);
            float zq[4] = {zv.x, zv.y, zv.z, zv.w};
            #pragma unroll
            for (int j = 0; j < 4; ++j) {
                const int d = 4 * i4 + j;
                float q = __ldg(eb + d);
                float diff = __fsub_rn(q, zq[j]);
                out[obase + (size_t)d * 1024] = __fadd_rn(zq[j], diff);  // STE: z + (q-z)
                lsum += (double)diff * (double)diff;
            }
        }
        out[OUT_IDX_OFF + (size_t)n] = (float)bidx;
    }

    // loss reduction (warps 0..3 carry data; all threads sync-safe)
    #pragma unroll
    for (int off = 16; off > 0; off >>= 1)
        lsum += __shfl_down_sync(0xFFFFFFFFu, lsum, off);
    if (lane == 0 && wid < 4) sRed[wid] = lsum;
    __syncthreads();
    if (tid == 0) {
        double v = sRed[0] + sRed[1] + sRed[2] + sRed[3];
        atomicAdd(&g_loss, v);
    }
}

// ---------------------------------------------------------------------------
// Finalize: loss = 1.25 * mean((q - z)^2)
// ---------------------------------------------------------------------------
__global__ void vq_fin(float* __restrict__ out) {
    if (threadIdx.x == 0 && blockIdx.x == 0) {
        double mean = g_loss / (double)OUT_QV_ELEMS;
        out[OUT_LOSS_OFF] = (float)(mean * 0.25 + mean * 1.0);
    }
}

extern "C" void kernel_launch(void* const* d_in, const int* in_sizes, int n_in,
                              void* d_out, int out_size) {
    const float* z   = (const float*)d_in[0];
    const float* emb = (const float*)d_in[1];
    float* out = (float*)d_out;

    vq_prep<<<(K_EMB * DIM + 255) / 256, 256>>>(emb);
    vq_main<<<N_Q / QB, THREADS>>>(z, emb, out);
    vq_fin<<<1, 32>>>(out);
}

// round 5
// speedup vs baseline: 2.9024x; 1.4926x over previous
#include <cuda_runtime.h>
#include <cuda_fp16.h>
#include <cstdint>

// Shapes
#define N_Q    65536
#define DIM    64
#define K_EMB  1024
#define QB     128        // queries per block (8 warps x 16 rows)
#define THREADS 256
#define NGROUP 128        // 1024 codes / 8 per n-group
#define PAD    68

#define ESCALE      1024.0f        // exact power-of-2 codebook scaling
#define INV_2SCALE  (1.0f / 512.0f)  // folds unscale into the 2*dot factor

#define OUT_QV_ELEMS  (64ULL * 64ULL * 32ULL * 32ULL)   // 4194304
#define OUT_IDX_OFF   4194304ULL
#define OUT_LOSS_OFF  4259840ULL

// device scratch (no cudaMalloc allowed)
__device__ double g_loss;
__device__ float  g_se2[K_EMB];
// Pre-packed B fragments for mma.m16n8k16.f16 (codebook scaled by 1024):
// index = (group*4 + kstep)*32 + lane ; .x = (k, k+1), .y = (k+8, k+9)
__device__ uint2  g_bh[NGROUP * 4 * 32];   // hi split
__device__ uint2  g_bm[NGROUP * 4 * 32];   // mid split

__device__ __forceinline__ uint32_t pack_h2(__half lo, __half hi) {
    return (uint32_t)__half_as_ushort(lo) | ((uint32_t)__half_as_ushort(hi) << 16);
}

__device__ __forceinline__ void mma_f16(float& d0, float& d1, float& d2, float& d3,
                                        uint32_t a0, uint32_t a1, uint32_t a2, uint32_t a3,
                                        uint32_t b0, uint32_t b1) {
    asm volatile(
        "mma.sync.aligned.m16n8k16.row.col.f32.f16.f16.f32 "
        "{%0,%1,%2,%3}, {%4,%5,%6,%7}, {%8,%9}, {%0,%1,%2,%3};\n"
        : "+f"(d0), "+f"(d1), "+f"(d2), "+f"(d3)
        : "r"(a0), "r"(a1), "r"(a2), "r"(a3), "r"(b0), "r"(b1));
}

// ---------------------------------------------------------------------------
// Prep: zero loss, ||e||^2 (square-then-add sequential), and pre-packed
// fp16 hi/mid B fragments of the 1024-scaled codebook.
// ---------------------------------------------------------------------------
__global__ void vq_prep(const float* __restrict__ emb) {
    int t = blockIdx.x * blockDim.x + threadIdx.x;
    if (t == 0) g_loss = 0.0;

    if (t < NGROUP * 4 * 32) {
        const int g   = t >> 7;          // n-group 0..127
        const int s   = (t >> 5) & 3;    // k-step 0..3
        const int l   = t & 31;
        const int gid = l >> 2;
        const int tig = l & 3;
        const int code = g * 8 + gid;
        const int k    = s * 16 + tig * 2;
        const float* e = emb + code * DIM;
        float v0 = e[k]     * ESCALE;
        float v1 = e[k + 1] * ESCALE;
        float v2 = e[k + 8] * ESCALE;
        float v3 = e[k + 9] * ESCALE;
        __half h0 = __float2half_rn(v0);
        __half h1 = __float2half_rn(v1);
        __half h2 = __float2half_rn(v2);
        __half h3 = __float2half_rn(v3);
        __half m0 = __float2half_rn(__fsub_rn(v0, __half2float(h0)));
        __half m1 = __float2half_rn(__fsub_rn(v1, __half2float(h1)));
        __half m2 = __float2half_rn(__fsub_rn(v2, __half2float(h2)));
        __half m3 = __float2half_rn(__fsub_rn(v3, __half2float(h3)));
        g_bh[t] = make_uint2(pack_h2(h0, h1), pack_h2(h2, h3));
        g_bm[t] = make_uint2(pack_h2(m0, m1), pack_h2(m2, m3));
    }
    if (t < K_EMB) {
        const float* e = emb + t * DIM;
        float s = 0.0f;
        #pragma unroll
        for (int j = 0; j < DIM; ++j)
            s = __fadd_rn(s, __fmul_rn(e[j], e[j]));
        g_se2[t] = s;
    }
}

// ---------------------------------------------------------------------------
// Main: 128 queries/block; dot_scaled = Z_f16split @ (1024*E)_f16split^T via
// 3-term mma.m16n8k16.f16; d2 = fl(fl(sz - dsum/512) + se) (exact reference
// rounding; /512 is exact); strict-< argmin + first-index tie-break.
// ---------------------------------------------------------------------------
__global__ void __launch_bounds__(THREADS, 2)
vq_main(const float* __restrict__ z,
        const float* __restrict__ emb,
        float* __restrict__ out) {
    __shared__ float  sBuf[QB * PAD];
    __shared__ float  sSe[K_EMB];
    __shared__ float  sSz[QB];
    __shared__ int    sIdx[QB];
    __shared__ double sRed[THREADS / 32];

    const int tid  = threadIdx.x;
    const int wid  = tid >> 5;
    const int lane = tid & 31;
    const int gid  = lane >> 2;
    const int tig  = lane & 3;
    const int qb   = blockIdx.x * QB;

    // ---- stage z tile + se ----
    {
        const float4* src = reinterpret_cast<const float4*>(z + (size_t)qb * DIM);
        #pragma unroll
        for (int i = tid; i < QB * (DIM / 4); i += THREADS) {
            int row = i >> 4, c4 = i & 15;
            float4 v = __ldg(src + row * (DIM / 4) + c4);
            *reinterpret_cast<float4*>(&sBuf[row * PAD + 4 * c4]) = v;
        }
        #pragma unroll
        for (int i = tid; i < K_EMB; i += THREADS) sSe[i] = g_se2[i];
    }
    __syncthreads();

    // row norms (square-then-add, sequential)
    if (tid < QB) {
        const float* r = &sBuf[tid * PAD];
        float s = 0.0f;
        #pragma unroll
        for (int j = 0; j < DIM; ++j)
            s = __fadd_rn(s, __fmul_rn(r[j], r[j]));
        sSz[tid] = s;
    }

    // ---- A fragments (fp16 hi & mid splits), rows r0=wid*16+gid, r1=r0+8 ----
    uint32_t aH[4][4], aM[4][4];
    const int r0 = wid * 16 + gid;
    const int r1 = r0 + 8;
    #pragma unroll
    for (int s = 0; s < 4; ++s) {
        const int k = s * 16 + tig * 2;
        const float v[4][2] = {
            { sBuf[r0 * PAD + k],     sBuf[r0 * PAD + k + 1] },
            { sBuf[r1 * PAD + k],     sBuf[r1 * PAD + k + 1] },
            { sBuf[r0 * PAD + k + 8], sBuf[r0 * PAD + k + 9] },
            { sBuf[r1 * PAD + k + 8], sBuf[r1 * PAD + k + 9] },
        };
        #pragma unroll
        for (int q = 0; q < 4; ++q) {
            __half h0 = __float2half_rn(v[q][0]);
            __half h1 = __float2half_rn(v[q][1]);
            __half m0 = __float2half_rn(__fsub_rn(v[q][0], __half2float(h0)));
            __half m1 = __float2half_rn(__fsub_rn(v[q][1], __half2float(h1)));
            aH[s][q] = pack_h2(h0, h1);
            aM[s][q] = pack_h2(m0, m1);
        }
    }
    __syncthreads();
    const float sz0 = sSz[r0];
    const float sz1 = sSz[r1];

    float best0 = 3.4e38f, best1 = 3.4e38f;
    int   idx0  = 0,       idx1  = 0;

    // ---- main loop over 128 n-groups of 8 codes ----
    #pragma unroll 2
    for (int g = 0; g < NGROUP; ++g) {
        uint2 bh[4], bm[4];
        #pragma unroll
        for (int s = 0; s < 4; ++s) {
            bh[s] = __ldg(&g_bh[(g * 4 + s) * 32 + lane]);
            bm[s] = __ldg(&g_bm[(g * 4 + s) * 32 + lane]);
        }
        float d0 = 0.f, d1 = 0.f, d2 = 0.f, d3 = 0.f;
        #pragma unroll
        for (int s = 0; s < 4; ++s)
            mma_f16(d0, d1, d2, d3, aH[s][0], aH[s][1], aH[s][2], aH[s][3], bh[s].x, bh[s].y);
        #pragma unroll
        for (int s = 0; s < 4; ++s)
            mma_f16(d0, d1, d2, d3, aH[s][0], aH[s][1], aH[s][2], aH[s][3], bm[s].x, bm[s].y);
        #pragma unroll
        for (int s = 0; s < 4; ++s)
            mma_f16(d0, d1, d2, d3, aM[s][0], aM[s][1], aM[s][2], aM[s][3], bh[s].x, bh[s].y);

        // epilogue: 2*dot = dsum/512 (exact), then reference rounding
        const int c0 = g * 8 + 2 * tig;
        const float se0 = sSe[c0], se1 = sSe[c0 + 1];
        float q00 = __fadd_rn(__fsub_rn(sz0, __fmul_rn(INV_2SCALE, d0)), se0);
        float q01 = __fadd_rn(__fsub_rn(sz0, __fmul_rn(INV_2SCALE, d1)), se1);
        float q10 = __fadd_rn(__fsub_rn(sz1, __fmul_rn(INV_2SCALE, d2)), se0);
        float q11 = __fadd_rn(__fsub_rn(sz1, __fmul_rn(INV_2SCALE, d3)), se1);
        if (q00 < best0) { best0 = q00; idx0 = c0; }
        if (q01 < best0) { best0 = q01; idx0 = c0 + 1; }
        if (q10 < best1) { best1 = q10; idx1 = c0; }
        if (q11 < best1) { best1 = q11; idx1 = c0 + 1; }
    }

    // ---- cross-lane argmin over the quad (cols), first-index tie-break ----
    #pragma unroll
    for (int off = 1; off <= 2; off <<= 1) {
        float ov0 = __shfl_xor_sync(0xFFFFFFFFu, best0, off);
        int   oi0 = __shfl_xor_sync(0xFFFFFFFFu, idx0, off);
        float ov1 = __shfl_xor_sync(0xFFFFFFFFu, best1, off);
        int   oi1 = __shfl_xor_sync(0xFFFFFFFFu, idx1, off);
        if (ov0 < best0 || (ov0 == best0 && oi0 < idx0)) { best0 = ov0; idx0 = oi0; }
        if (ov1 < best1 || (ov1 == best1 && oi1 < idx1)) { best1 = ov1; idx1 = oi1; }
    }
    if (tig == 0) {
        sIdx[wid * 16 + gid]     = idx0;
        sIdx[wid * 16 + gid + 8] = idx1;
    }
    __syncthreads();

    // ---- outputs: gather, STE, idx, loss ----
    double lsum = 0.0;
    if (tid < QB) {
        const int n = qb + tid;
        const int bidx = sIdx[tid];
        const int w = n & 31;
        const int h = (n >> 5) & 31;
        const int b = n >> 10;
        const size_t obase = (size_t)b * 65536 + (size_t)h * 32 + w;

        const float4* zrow = reinterpret_cast<const float4*>(z + (size_t)n * DIM);
        const float*  eb   = emb + (size_t)bidx * DIM;
        #pragma unroll
        for (int i4 = 0; i4 < DIM / 4; ++i4) {
            float4 zv = __ldg(zrow + i4);
            float zq[4] = {zv.x, zv.y, zv.z, zv.w};
            #pragma unroll
            for (int j = 0; j < 4; ++j) {
                const int d = 4 * i4 + j;
                float q = __ldg(eb + d);
                float diff = __fsub_rn(q, zq[j]);
                out[obase + (size_t)d * 1024] = __fadd_rn(zq[j], diff);  // STE
                lsum += (double)diff * (double)diff;
            }
        }
        out[OUT_IDX_OFF + (size_t)n] = (float)bidx;
    }

    // ---- loss reduction ----
    #pragma unroll
    for (int off = 16; off > 0; off >>= 1)
        lsum += __shfl_down_sync(0xFFFFFFFFu, lsum, off);
    if (lane == 0) sRed[wid] = lsum;
    __syncthreads();
    if (tid == 0) {
        double v = 0.0;
        #pragma unroll
        for (int i = 0; i < THREADS / 32; ++i) v += sRed[i];
        atomicAdd(&g_loss, v);
    }
}

// ---------------------------------------------------------------------------
__global__ void vq_fin(float* __restrict__ out) {
    if (threadIdx.x == 0 && blockIdx.x == 0) {
        double mean = g_loss / (double)OUT_QV_ELEMS;
        out[OUT_LOSS_OFF] = (float)(mean * 0.25 + mean * 1.0);
    }
}

extern "C" void kernel_launch(void* const* d_in, const int* in_sizes, int n_in,
                              void* d_out, int out_size) {
    const float* z   = (const float*)d_in[0];
    const float* emb = (const float*)d_in[1];
    float* out = (float*)d_out;

    vq_prep<<<(NGROUP * 4 * 32 + 255) / 256, 256>>>(emb);
    vq_main<<<N_Q / QB, THREADS>>>(z, emb, out);
    vq_fin<<<1, 32>>>(out);
}